// round 5
// baseline (speedup 1.0000x reference)
#include <cuda_runtime.h>
#include <cuda_bf16.h>

#define BATCH 32
#define HW 56
#define EMB 256
#define NHEAD 8
#define HDIM 32
#define NWIN 64
#define WS 7
#define SSH 3
#define WD 49
#define NPOS 3136

// attention output in final (un-shifted) token order
__device__ float g_Y[(size_t)BATCH * NPOS * EMB];

// ---------------- fused kernel smem layout (floats) ----------------
#define QS_PITCH 33
#define AT_PITCH 52
#define OFF_XS   0
#define OFF_QS   (WD * EMB)                               // 12544
#define REGION0  (OFF_QS + NHEAD * WD * QS_PITCH)         // 25480 (xs+Qs; AT overlays)
#define OFF_KS   REGION0
#define OFF_VS   (OFF_KS + NHEAD * WD * HDIM)
#define OFF_RPB  (OFF_VS + NHEAD * WD * HDIM)
#define OFF_INV  (OFF_RPB + NHEAD * 169)
#define OFF_KOFF (OFF_INV + NHEAD * WD)
#define OFF_REG  (OFF_KOFF + WD)
#define OFF_POS  (OFF_REG + WD)
#define SMEM_FLOATS (OFF_POS + WD)
#define SMEM_BYTES  (SMEM_FLOATS * 4)     // ~209.8 KB

__device__ __forceinline__ void win_token(int w, int t, int& pos, int& reg)
{
    const int wi = w >> 3, wj = w & 7;
    int a = t / 7, c = t % 7;
    int hh = wi * 7 + a;                 // coordinate in SHIFTED image
    int ww = wj * 7 + c;
    int row = hh + SSH; if (row >= HW) row -= HW;   // original coords
    int col = ww + SSH; if (col >= HW) col -= HW;
    pos = row * HW + col;
    int fh = hh < HW - WS ? 0 : (hh < HW - SSH ? 1 : 2);
    int fw = ww < HW - WS ? 0 : (ww < HW - SSH ? 1 : 2);
    reg = fh * 3 + fw;
}

// ---------------------------------------------------------------------------
// Fused QKV + windowed attention. grid = B*NW = 2048, 256 threads.
// Warp h owns head h end-to-end; Q/K/V live only in shared memory.
// ---------------------------------------------------------------------------
__global__ void __launch_bounds__(256, 1) fused_attn_kernel(
    const float* __restrict__ x,      // (B,3136,256)
    const float* __restrict__ qkv_w,  // (32,96)
    const float* __restrict__ qkv_b,  // (96,)
    const float* __restrict__ rpb)    // (169,8)
{
    extern __shared__ float sm[];
    float* xs    = sm + OFF_XS;    // [49][256]   (dead after phase 1)
    float* Qs    = sm + OFF_QS;    // [8][49][33] (dead after qreg load)
    float* AT    = sm + OFF_XS;    // [8][49][52] overlays xs+Qs
    float* Ks    = sm + OFF_KS;    // [8][49][32]
    float* Vs    = sm + OFF_VS;    // [8][49][32]
    float* rpb_s = sm + OFF_RPB;   // [8][169]
    float* inv_s = sm + OFF_INV;   // [8][49]
    int* koff_s  = (int*)(sm + OFF_KOFF);
    int* reg_s   = (int*)(sm + OFF_REG);
    int* pos_s   = (int*)(sm + OFF_POS);

    const int blk = blockIdx.x;
    const int b = blk >> 6, w = blk & (NWIN - 1);
    const int t = threadIdx.x;
    const int h = t >> 5, ln = t & 31;

    if (t < WD) {
        int p, r; win_token(w, t, p, r);
        pos_s[t] = p; reg_s[t] = r;
        koff_s[t] = (t / 7) * 13 + (t % 7);
    }
    for (int i = t; i < NHEAD * 169; i += 256) {
        int hh = i / 169, idx = i - hh * 169;
        rpb_s[i] = rpb[idx * NHEAD + hh];
    }
    __syncthreads();

    // ---- stage x window (49 x 256) ----
    {
        const float* xb = x + (size_t)b * NPOS * EMB;
        for (int i = t; i < WD * 64; i += 256) {
            int tok = i >> 6, c = i & 63;
            ((float4*)(xs + tok * EMB))[c] =
                ((const float4*)(xb + (size_t)pos_s[tok] * EMB))[c];
        }
    }

    // ---- per-thread weight columns ----
    float wq[HDIM], wk[HDIM], wv[HDIM];
    #pragma unroll
    for (int kk = 0; kk < HDIM; kk++) {
        wq[kk] = __ldg(&qkv_w[kk * 96 + ln]);
        wk[kk] = __ldg(&qkv_w[kk * 96 + 32 + ln]);
        wv[kk] = __ldg(&qkv_w[kk * 96 + 64 + ln]);
    }
    const float bqv = __ldg(&qkv_b[ln]);
    const float bkv = __ldg(&qkv_b[32 + ln]);
    const float bvv = __ldg(&qkv_b[64 + ln]);
    __syncthreads();   // xs ready

    // ---- phase 1: QKV into smem ----
    {
        float* q_dst = Qs + h * WD * QS_PITCH;
        float* k_dst = Ks + h * WD * HDIM;
        float* v_dst = Vs + h * WD * HDIM;
        #pragma unroll 7
        for (int tok = 0; tok < WD; tok++) {
            const float4* xr = (const float4*)(xs + tok * EMB + h * HDIM);
            float aq = bqv, ak = bkv, av = bvv;
            #pragma unroll
            for (int j = 0; j < 8; j++) {
                float4 xv = xr[j];
                aq += xv.x*wq[j*4+0] + xv.y*wq[j*4+1] + xv.z*wq[j*4+2] + xv.w*wq[j*4+3];
                ak += xv.x*wk[j*4+0] + xv.y*wk[j*4+1] + xv.z*wk[j*4+2] + xv.w*wk[j*4+3];
                av += xv.x*wv[j*4+0] + xv.y*wv[j*4+1] + xv.z*wv[j*4+2] + xv.w*wv[j*4+3];
            }
            q_dst[tok * QS_PITCH + ln] = aq * 0.17677669529663688f;  // 1/sqrt(32)
            k_dst[tok * HDIM + ln] = ak;
            v_dst[tok * HDIM + ln] = av;
        }
    }
    __syncwarp();

    // ---- load this lane's q-rows into registers ----
    const int q0 = ln, q1 = ln + 32;
    const bool has2 = (q1 < WD);
    float qa[HDIM], qb[HDIM];
    {
        const float* q_src = Qs + h * WD * QS_PITCH;
        #pragma unroll
        for (int d = 0; d < HDIM; d++) qa[d] = q_src[q0 * QS_PITCH + d];
        #pragma unroll
        for (int d = 0; d < HDIM; d++) qb[d] = has2 ? q_src[q1 * QS_PITCH + d] : 0.0f;
    }
    __syncthreads();   // xs & Qs dead -> AT overlay is now safe block-wide

    // ---- phase 2: scores (transposed store) with online row max ----
    float m0 = -1e30f, m1 = -1e30f;
    const int rb0 = (q0 / 7 + 6) * 13 + (q0 % 7 + 6);
    const int rq0 = reg_s[q0];
    int rb1 = 0, rq1 = 0;
    if (has2) { rb1 = (q1 / 7 + 6) * 13 + (q1 % 7 + 6); rq1 = reg_s[q1]; }

    {
        const float* kh = Ks + h * WD * HDIM;
        float* at = AT + h * WD * AT_PITCH;
        const float* rh = rpb_s + h * 169;
        for (int k = 0; k < WD; k++) {
            const float4* kr = (const float4*)(kh + k * HDIM);
            float p00=0.f,p01=0.f,p02=0.f,p03=0.f;
            float p10=0.f,p11=0.f,p12=0.f,p13=0.f;
            #pragma unroll
            for (int j = 0; j < 8; j++) {
                float4 kv = kr[j];
                p00 += qa[4*j+0]*kv.x; p01 += qa[4*j+1]*kv.y;
                p02 += qa[4*j+2]*kv.z; p03 += qa[4*j+3]*kv.w;
                p10 += qb[4*j+0]*kv.x; p11 += qb[4*j+1]*kv.y;
                p12 += qb[4*j+2]*kv.z; p13 += qb[4*j+3]*kv.w;
            }
            const int ko = koff_s[k];
            const int rk = reg_s[k];
            float s0 = (p00 + p01) + (p02 + p03);
            s0 += rh[rb0 - ko] + (rk != rq0 ? -100.0f : 0.0f);
            at[k * AT_PITCH + q0] = s0;
            m0 = fmaxf(m0, s0);
            if (has2) {
                float s1 = (p10 + p11) + (p12 + p13);
                s1 += rh[rb1 - ko] + (rk != rq1 ? -100.0f : 0.0f);
                at[k * AT_PITCH + q1] = s1;
                m1 = fmaxf(m1, s1);
            }
        }
    }
    // lane reads only its own columns next -> no sync needed yet

    // ---- phase 3: per-lane softmax (exp + sum; 1/sum deferred) ----
    {
        float* at = AT + h * WD * AT_PITCH;
        float sum0 = 0.f, sum1 = 0.f;
        for (int k = 0; k < WD; k++) {
            float e0 = __expf(at[k * AT_PITCH + q0] - m0);
            sum0 += e0;
            at[k * AT_PITCH + q0] = e0;
            if (has2) {
                float e1 = __expf(at[k * AT_PITCH + q1] - m1);
                sum1 += e1;
                at[k * AT_PITCH + q1] = e1;
            }
        }
        inv_s[h * WD + q0] = 1.0f / sum0;
        if (has2) inv_s[h * WD + q1] = 1.0f / sum1;
    }
    __syncwarp();

    // ---- phase 4: O = A @ V (lane = dim), scaled by inv, scatter to g_Y ----
    {
        const float* vh = Vs + h * WD * HDIM;
        const float* at = AT + h * WD * AT_PITCH;
        const float* iv = inv_s + h * WD;
        float* yb = g_Y + (size_t)b * NPOS * EMB + h * HDIM + ln;
        #pragma unroll 13
        for (int g = 0; g < 13; g++) {
            const int qv = g * 4;
            float a0=0.f,a1=0.f,a2=0.f,a3=0.f;
            for (int k = 0; k < WD; k++) {
                float vv = vh[k * HDIM + ln];
                float4 aa = *(const float4*)(at + k * AT_PITCH + qv);
                a0 += aa.x * vv; a1 += aa.y * vv;
                a2 += aa.z * vv; a3 += aa.w * vv;
            }
            yb[(size_t)pos_s[qv] * EMB] = a0 * iv[qv];
            if (qv + 1 < WD) {
                yb[(size_t)pos_s[qv+1] * EMB] = a1 * iv[qv+1];
                yb[(size_t)pos_s[qv+2] * EMB] = a2 * iv[qv+2];
                yb[(size_t)pos_s[qv+3] * EMB] = a3 * iv[qv+3];
            }
        }
    }
}

// ---------------------------------------------------------------------------
// Kernel 2: out = Y @ proj_w + proj_b  (M=100352, N=256, K=256)  (unchanged)
// ---------------------------------------------------------------------------
__global__ __launch_bounds__(256) void proj_kernel(
    const float* __restrict__ Wg,
    const float* __restrict__ bg,
    float* __restrict__ out)
{
    const int t  = threadIdx.x;
    const int tx = t & 15;
    const int ty = t >> 4;
    const int n0 = blockIdx.x * 128;
    const int m0 = blockIdx.y * 128;

    __shared__ float As[16][128];
    __shared__ float Bs[16][128];

    float acc[8][8];
    #pragma unroll
    for (int i = 0; i < 8; i++)
        #pragma unroll
        for (int j = 0; j < 8; j++) acc[i][j] = 0.0f;

    const float* Ybase = g_Y + (size_t)m0 * EMB;

    float4 pa[2], pb[2];

    auto fetchA = [&](int kt, int i) -> float4 {
        int f = t * 2 + i;
        int m = f >> 2, kq = (f & 3) * 4;
        return *(const float4*)(Ybase + (size_t)m * EMB + kt * 16 + kq);
    };
    auto fetchB = [&](int kt, int i) -> float4 {
        int f = t * 2 + i;
        int kr = f >> 5, c4 = (f & 31) * 4;
        return *(const float4*)(Wg + (size_t)(kt * 16 + kr) * EMB + n0 + c4);
    };
    auto storeA = [&](int i, float4 v) {
        int f = t * 2 + i;
        int m = f >> 2, kq = (f & 3) * 4;
        As[kq + 0][m] = v.x; As[kq + 1][m] = v.y;
        As[kq + 2][m] = v.z; As[kq + 3][m] = v.w;
    };
    auto storeB = [&](int i, float4 v) {
        int f = t * 2 + i;
        int kr = f >> 5, c4 = (f & 31) * 4;
        *(float4*)&Bs[kr][c4] = v;
    };

    storeA(0, fetchA(0, 0)); storeA(1, fetchA(0, 1));
    storeB(0, fetchB(0, 0)); storeB(1, fetchB(0, 1));
    __syncthreads();

    for (int kt = 0; kt < 16; kt++) {
        if (kt < 15) {
            pa[0] = fetchA(kt + 1, 0); pa[1] = fetchA(kt + 1, 1);
            pb[0] = fetchB(kt + 1, 0); pb[1] = fetchB(kt + 1, 1);
        }
        #pragma unroll
        for (int kk = 0; kk < 16; kk++) {
            float4 a0 = *(float4*)&As[kk][ty * 4];
            float4 a1 = *(float4*)&As[kk][ty * 4 + 64];
            float4 b0 = *(float4*)&Bs[kk][tx * 4];
            float4 b1 = *(float4*)&Bs[kk][tx * 4 + 64];
            float ar[8] = {a0.x, a0.y, a0.z, a0.w, a1.x, a1.y, a1.z, a1.w};
            float br[8] = {b0.x, b0.y, b0.z, b0.w, b1.x, b1.y, b1.z, b1.w};
            #pragma unroll
            for (int i = 0; i < 8; i++)
                #pragma unroll
                for (int j = 0; j < 8; j++) acc[i][j] += ar[i] * br[j];
        }
        __syncthreads();
        if (kt < 15) {
            storeA(0, pa[0]); storeA(1, pa[1]);
            storeB(0, pb[0]); storeB(1, pb[1]);
            __syncthreads();
        }
    }

    float4 bb0 = *(const float4*)(bg + n0 + tx * 4);
    float4 bb1 = *(const float4*)(bg + n0 + tx * 4 + 64);
    #pragma unroll
    for (int i = 0; i < 8; i++) {
        int m = m0 + ty * 4 + (i < 4 ? i : 60 + i);
        float4 o0, o1;
        o0.x = acc[i][0] + bb0.x; o0.y = acc[i][1] + bb0.y;
        o0.z = acc[i][2] + bb0.z; o0.w = acc[i][3] + bb0.w;
        o1.x = acc[i][4] + bb1.x; o1.y = acc[i][5] + bb1.y;
        o1.z = acc[i][6] + bb1.z; o1.w = acc[i][7] + bb1.w;
        *(float4*)(out + (size_t)m * EMB + n0 + tx * 4)      = o0;
        *(float4*)(out + (size_t)m * EMB + n0 + tx * 4 + 64) = o1;
    }
}

extern "C" void kernel_launch(void* const* d_in, const int* in_sizes, int n_in,
                              void* d_out, int out_size)
{
    const float* x      = (const float*)d_in[0];
    const float* qkv_w  = (const float*)d_in[1];
    const float* qkv_b  = (const float*)d_in[2];
    const float* proj_w = (const float*)d_in[3];
    const float* proj_b = (const float*)d_in[4];
    const float* rpb    = (const float*)d_in[5];
    float* out = (float*)d_out;

    cudaFuncSetAttribute(fused_attn_kernel,
                         cudaFuncAttributeMaxDynamicSharedMemorySize, SMEM_BYTES);
    fused_attn_kernel<<<BATCH * NWIN, 256, SMEM_BYTES>>>(x, qkv_w, qkv_b, rpb);
    proj_kernel<<<dim3(EMB / 128, (BATCH * NPOS) / 128), 256>>>(proj_w, proj_b, out);
}